// round 8
// baseline (speedup 1.0000x reference)
#include <cuda_runtime.h>
#include <cuda_fp16.h>
#include <cuda_bf16.h>
#include <cstdint>

// ---------------- problem constants ----------------
#define MAXN    100000
#define MAXE    3200000
#define NFEAT   512
#define HID     64
#define NCLASS  64
#define ALPHA   0.1f
#define NITER   10
#define SCAN_BLK 1024

// ---------------- static device scratch ----------------
__device__ float  g_z0[MAXN * NCLASS];     // fp32 base prediction
__device__ __half g_ya[MAXN * NCLASS];     // fp16 scaled z ping
__device__ __half g_yb[MAXN * NCLASS];     // fp16 scaled z pong
__device__ int    g_rowptr[MAXN + 1];
__device__ int    g_cursor[MAXN];
__device__ int    g_bsums[128];
__device__ int2   g_edges[MAXE];

// ================= mma.sync helpers (baseline sm_80+, works on sm_103) ====
__device__ __forceinline__ uint32_t smem_u32(const void* p) {
    uint32_t a;
    asm("{ .reg .u64 t; cvta.to.shared.u64 t, %1; cvt.u32.u64 %0, t; }"
        : "=r"(a) : "l"(p));
    return a;
}
__device__ __forceinline__ void ldsm_x4(uint32_t* r, uint32_t addr) {
    asm volatile("ldmatrix.sync.aligned.m8n8.x4.shared.b16 {%0,%1,%2,%3}, [%4];"
                 : "=r"(r[0]), "=r"(r[1]), "=r"(r[2]), "=r"(r[3]) : "r"(addr));
}
__device__ __forceinline__ void ldsm_x4_t(uint32_t* r, uint32_t addr) {
    asm volatile("ldmatrix.sync.aligned.m8n8.x4.trans.shared.b16 {%0,%1,%2,%3}, [%4];"
                 : "=r"(r[0]), "=r"(r[1]), "=r"(r[2]), "=r"(r[3]) : "r"(addr));
}
__device__ __forceinline__ void mma_bf16(
    float* d, const uint32_t* a, const uint32_t* b)
{
    asm volatile(
        "mma.sync.aligned.m16n8k16.row.col.f32.bf16.bf16.f32 "
        "{%0,%1,%2,%3}, {%4,%5,%6,%7}, {%8,%9}, {%0,%1,%2,%3};"
        : "+f"(d[0]), "+f"(d[1]), "+f"(d[2]), "+f"(d[3])
        : "r"(a[0]), "r"(a[1]), "r"(a[2]), "r"(a[3]), "r"(b[0]), "r"(b[1]));
}
__device__ __forceinline__ uint32_t pkbf2(float a, float b) {
    __nv_bfloat162 h = __floats2bfloat162_rn(a, b);
    return *reinterpret_cast<uint32_t*>(&h);
}

// =================================================================
// mma.sync fused GEMM: z0 = relu(x @ W1) @ W2, bf16 hi/lo 3-term split.
// =================================================================
#define GM_AHI 0
#define GM_ALO 36864
#define GM_BHI 73728
#define GM_BLO 82944
#define GM_SMEM 92160

__global__ __launch_bounds__(256) void gemm_mma(
    const float* __restrict__ X, const float* __restrict__ W1,
    const float* __restrict__ W2, float* __restrict__ Z0, int n)
{
    extern __shared__ char smc[];
    const uint32_t sb = smem_u32(smc);
    const int tid = threadIdx.x;
    const int wid = tid >> 5;
    const int l   = tid & 31;
    const int bm  = blockIdx.x * 256;
    const int wr  = wid * 32;

    const int arow = (l & 7) + ((l >> 3) & 1) * 8;
    const uint32_t akb = ((l >> 4) & 1) * 16;
    const uint32_t aoff0 = (uint32_t)(wr + arow) * 144 + akb;
    const uint32_t aoff1 = (uint32_t)(wr + 16 + arow) * 144 + akb;
    const uint32_t boff  = (uint32_t)arow * 144 + akb;

    float acc[2][8][4];
#pragma unroll
    for (int am = 0; am < 2; am++)
#pragma unroll
        for (int na = 0; na < 8; na++)
#pragma unroll
            for (int q = 0; q < 4; q++) acc[am][na][q] = 0.f;

    for (int c = 0; c < 8; c++) {
#pragma unroll
        for (int it = 0; it < 16; it++) {
            int idx = it * 256 + tid;
            int r   = idx >> 4;
            int c4  = idx & 15;
            int row = bm + r;
            float4 v = make_float4(0.f, 0.f, 0.f, 0.f);
            if (row < n)
                v = *reinterpret_cast<const float4*>(X + (size_t)row * NFEAT + c * 64 + c4 * 4);
            uint32_t h0 = pkbf2(v.x, v.y), h1 = pkbf2(v.z, v.w);
            __nv_bfloat162 bh0 = *reinterpret_cast<__nv_bfloat162*>(&h0);
            __nv_bfloat162 bh1 = *reinterpret_cast<__nv_bfloat162*>(&h1);
            float2 f0 = __bfloat1622float2(bh0);
            float2 f1 = __bfloat1622float2(bh1);
            uint32_t l0 = pkbf2(v.x - f0.x, v.y - f0.y);
            uint32_t l1 = pkbf2(v.z - f1.x, v.w - f1.y);
            uint32_t off = (uint32_t)r * 144 + c4 * 8;
            *reinterpret_cast<uint2*>(smc + GM_AHI + off) = make_uint2(h0, h1);
            *reinterpret_cast<uint2*>(smc + GM_ALO + off) = make_uint2(l0, l1);
        }
#pragma unroll
        for (int it = 0; it < 4; it++) {
            int idx = it * 256 + tid;
            int k   = idx >> 4;
            int c4  = idx & 15;
            float4 v = *reinterpret_cast<const float4*>(W1 + (size_t)(c * 64 + k) * HID + c4 * 4);
            uint32_t h0 = pkbf2(v.x, v.y), h1 = pkbf2(v.z, v.w);
            __nv_bfloat162 bh0 = *reinterpret_cast<__nv_bfloat162*>(&h0);
            __nv_bfloat162 bh1 = *reinterpret_cast<__nv_bfloat162*>(&h1);
            float2 f0 = __bfloat1622float2(bh0);
            float2 f1 = __bfloat1622float2(bh1);
            uint32_t l0 = pkbf2(v.x - f0.x, v.y - f0.y);
            uint32_t l1 = pkbf2(v.z - f1.x, v.w - f1.y);
            uint32_t off = (uint32_t)k * 144 + c4 * 8;
            *reinterpret_cast<uint2*>(smc + GM_BHI + off) = make_uint2(h0, h1);
            *reinterpret_cast<uint2*>(smc + GM_BLO + off) = make_uint2(l0, l1);
        }
        __syncthreads();

#pragma unroll
        for (int s = 0; s < 4; s++) {
            uint32_t ah0[4], ah1[4], al0[4], al1[4];
            ldsm_x4(ah0, sb + GM_AHI + aoff0 + s * 32);
            ldsm_x4(ah1, sb + GM_AHI + aoff1 + s * 32);
            ldsm_x4(al0, sb + GM_ALO + aoff0 + s * 32);
            ldsm_x4(al1, sb + GM_ALO + aoff1 + s * 32);
            uint32_t bh[8][2], bl[8][2];
#pragma unroll
            for (int p = 0; p < 4; p++) {
                uint32_t r4[4];
                ldsm_x4_t(r4, sb + GM_BHI + s * 2304 + p * 32 + boff);
                bh[2 * p][0] = r4[0]; bh[2 * p][1] = r4[1];
                bh[2 * p + 1][0] = r4[2]; bh[2 * p + 1][1] = r4[3];
                ldsm_x4_t(r4, sb + GM_BLO + s * 2304 + p * 32 + boff);
                bl[2 * p][0] = r4[0]; bl[2 * p][1] = r4[1];
                bl[2 * p + 1][0] = r4[2]; bl[2 * p + 1][1] = r4[3];
            }
#pragma unroll
            for (int na = 0; na < 8; na++) {
                mma_bf16(acc[0][na], ah0, bh[na]);
                mma_bf16(acc[1][na], ah1, bh[na]);
                mma_bf16(acc[0][na], al0, bh[na]);
                mma_bf16(acc[1][na], al1, bh[na]);
                mma_bf16(acc[0][na], ah0, bl[na]);
                mma_bf16(acc[1][na], ah1, bl[na]);
            }
        }
        __syncthreads();
    }

    // ---- phase 2 ----
    uint32_t a2h[2][4][4], a2l[2][4][4];
#pragma unroll
    for (int am = 0; am < 2; am++)
#pragma unroll
        for (int s = 0; s < 4; s++) {
            float v00 = fmaxf(acc[am][2 * s][0], 0.f);
            float v01 = fmaxf(acc[am][2 * s][1], 0.f);
            float v02 = fmaxf(acc[am][2 * s][2], 0.f);
            float v03 = fmaxf(acc[am][2 * s][3], 0.f);
            float v10 = fmaxf(acc[am][2 * s + 1][0], 0.f);
            float v11 = fmaxf(acc[am][2 * s + 1][1], 0.f);
            float v12 = fmaxf(acc[am][2 * s + 1][2], 0.f);
            float v13 = fmaxf(acc[am][2 * s + 1][3], 0.f);
            uint32_t h;
            h = pkbf2(v00, v01); a2h[am][s][0] = h;
            { __nv_bfloat162 b = *reinterpret_cast<__nv_bfloat162*>(&h); float2 f = __bfloat1622float2(b);
              a2l[am][s][0] = pkbf2(v00 - f.x, v01 - f.y); }
            h = pkbf2(v02, v03); a2h[am][s][1] = h;
            { __nv_bfloat162 b = *reinterpret_cast<__nv_bfloat162*>(&h); float2 f = __bfloat1622float2(b);
              a2l[am][s][1] = pkbf2(v02 - f.x, v03 - f.y); }
            h = pkbf2(v10, v11); a2h[am][s][2] = h;
            { __nv_bfloat162 b = *reinterpret_cast<__nv_bfloat162*>(&h); float2 f = __bfloat1622float2(b);
              a2l[am][s][2] = pkbf2(v10 - f.x, v11 - f.y); }
            h = pkbf2(v12, v13); a2h[am][s][3] = h;
            { __nv_bfloat162 b = *reinterpret_cast<__nv_bfloat162*>(&h); float2 f = __bfloat1622float2(b);
              a2l[am][s][3] = pkbf2(v12 - f.x, v13 - f.y); }
        }

#pragma unroll
    for (int am = 0; am < 2; am++)
#pragma unroll
        for (int na = 0; na < 8; na++)
#pragma unroll
            for (int q = 0; q < 4; q++) acc[am][na][q] = 0.f;

#pragma unroll
    for (int it = 0; it < 4; it++) {
        int idx = it * 256 + tid;
        int k   = idx >> 4;
        int c4  = idx & 15;
        float4 v = *reinterpret_cast<const float4*>(W2 + (size_t)k * NCLASS + c4 * 4);
        uint32_t h0 = pkbf2(v.x, v.y), h1 = pkbf2(v.z, v.w);
        __nv_bfloat162 bh0 = *reinterpret_cast<__nv_bfloat162*>(&h0);
        __nv_bfloat162 bh1 = *reinterpret_cast<__nv_bfloat162*>(&h1);
        float2 f0 = __bfloat1622float2(bh0);
        float2 f1 = __bfloat1622float2(bh1);
        uint32_t l0 = pkbf2(v.x - f0.x, v.y - f0.y);
        uint32_t l1 = pkbf2(v.z - f1.x, v.w - f1.y);
        uint32_t off = (uint32_t)k * 144 + c4 * 8;
        *reinterpret_cast<uint2*>(smc + GM_BHI + off) = make_uint2(h0, h1);
        *reinterpret_cast<uint2*>(smc + GM_BLO + off) = make_uint2(l0, l1);
    }
    __syncthreads();

#pragma unroll
    for (int s = 0; s < 4; s++) {
        uint32_t bh[8][2], bl[8][2];
#pragma unroll
        for (int p = 0; p < 4; p++) {
            uint32_t r4[4];
            ldsm_x4_t(r4, sb + GM_BHI + s * 2304 + p * 32 + boff);
            bh[2 * p][0] = r4[0]; bh[2 * p][1] = r4[1];
            bh[2 * p + 1][0] = r4[2]; bh[2 * p + 1][1] = r4[3];
            ldsm_x4_t(r4, sb + GM_BLO + s * 2304 + p * 32 + boff);
            bl[2 * p][0] = r4[0]; bl[2 * p][1] = r4[1];
            bl[2 * p + 1][0] = r4[2]; bl[2 * p + 1][1] = r4[3];
        }
#pragma unroll
        for (int na = 0; na < 8; na++) {
            mma_bf16(acc[0][na], a2h[0][s], bh[na]);
            mma_bf16(acc[1][na], a2h[1][s], bh[na]);
            mma_bf16(acc[0][na], a2l[0][s], bh[na]);
            mma_bf16(acc[1][na], a2l[1][s], bh[na]);
            mma_bf16(acc[0][na], a2h[0][s], bl[na]);
            mma_bf16(acc[1][na], a2h[1][s], bl[na]);
        }
    }

#pragma unroll
    for (int am = 0; am < 2; am++) {
        int r0 = bm + wr + am * 16 + (l >> 2);
        int col = (l & 3) * 2;
#pragma unroll
        for (int na = 0; na < 8; na++) {
            if (r0 < n)
                *reinterpret_cast<float2*>(Z0 + (size_t)r0 * NCLASS + na * 8 + col) =
                    make_float2(acc[am][na][0], acc[am][na][1]);
            if (r0 + 8 < n)
                *reinterpret_cast<float2*>(Z0 + (size_t)(r0 + 8) * NCLASS + na * 8 + col) =
                    make_float2(acc[am][na][2], acc[am][na][3]);
        }
    }
}

// =================================================================
// CSR construction
// =================================================================
__global__ __launch_bounds__(256) void hist_dst(
    const int* __restrict__ dst, int* __restrict__ cnt, int e)
{
    int i = blockIdx.x * 256 + threadIdx.x;
    if (i < e) atomicAdd(&cnt[dst[i]], 1);
}

__global__ __launch_bounds__(SCAN_BLK) void scan1(
    const int* __restrict__ cnt, int* __restrict__ rowptr,
    int* __restrict__ bsums, int n)
{
    __shared__ int sh[SCAN_BLK];
    int t = threadIdx.x;
    int i = blockIdx.x * SCAN_BLK + t;
    int v = (i < n) ? cnt[i] : 0;
    sh[t] = v;
    __syncthreads();
#pragma unroll
    for (int off = 1; off < SCAN_BLK; off <<= 1) {
        int x = (t >= off) ? sh[t - off] : 0;
        __syncthreads();
        sh[t] += x;
        __syncthreads();
    }
    int incl = sh[t];
    if (i < n) rowptr[i] = incl - v;
    if (t == SCAN_BLK - 1) bsums[blockIdx.x] = incl;
}

__global__ __launch_bounds__(128) void scan2(int* __restrict__ bsums, int nb)
{
    __shared__ int sh[128];
    int t = threadIdx.x;
    int v = (t < nb) ? bsums[t] : 0;
    sh[t] = v;
    __syncthreads();
#pragma unroll
    for (int off = 1; off < 128; off <<= 1) {
        int x = (t >= off) ? sh[t - off] : 0;
        __syncthreads();
        sh[t] += x;
        __syncthreads();
    }
    if (t < nb) bsums[t] = sh[t] - v;
}

__global__ __launch_bounds__(256) void scan3(
    int* __restrict__ rowptr, int* __restrict__ cursor,
    const int* __restrict__ bsums, int n, int e)
{
    int i = blockIdx.x * 256 + threadIdx.x;
    if (i < n) {
        int v = rowptr[i] + bsums[i >> 10];
        rowptr[i] = v;
        cursor[i] = v;
    }
    if (i == n) rowptr[n] = e;
}

__global__ __launch_bounds__(256) void build_edges(
    const int* __restrict__ src, const int* __restrict__ dst,
    const float* __restrict__ ew, int* __restrict__ cursor,
    int2* __restrict__ edges, int e)
{
    int i = blockIdx.x * 256 + threadIdx.x;
    if (i < e) {
        int d = dst[i];
        int pos = atomicAdd(&cursor[d], 1);
        edges[pos] = make_int2(src[i], __float_as_int(ew[i]));
    }
}

// =================================================================
// gather (scaled fp16 pipeline): one warp per dst node.
// 4 sub-groups of 8 lanes; 4-deep unroll => 16 rows in flight/warp.
// =================================================================
__device__ __forceinline__ void load_row8_h(
    const __half* zin, int node, int c8, float* v)
{
    float4 raw = __ldg(reinterpret_cast<const float4*>(zin + (size_t)node * NCLASS) + c8);
    const __half2* h = reinterpret_cast<const __half2*>(&raw);
#pragma unroll
    for (int j = 0; j < 4; j++) {
        float2 f = __half22float2(h[j]);
        v[2 * j]     = f.x;
        v[2 * j + 1] = f.y;
    }
}
__device__ __forceinline__ void load_row8_f(
    const float* zin, int node, int c8, float* v)
{
    const float4* p = reinterpret_cast<const float4*>(zin + (size_t)node * NCLASS);
    float4 a = __ldg(p + 2 * c8);
    float4 b = __ldg(p + 2 * c8 + 1);
    v[0] = a.x; v[1] = a.y; v[2] = a.z; v[3] = a.w;
    v[4] = b.x; v[5] = b.y; v[6] = b.z; v[7] = b.w;
}

template<bool IN_HALF, bool LAST>
__global__ __launch_bounds__(256) void gather_nodes(
    const int2* __restrict__ edges, const int* __restrict__ rowptr,
    const void* __restrict__ zin_v, const float* __restrict__ z0,
    void* __restrict__ zout_v, float c1, float c0, int n)
{
    int warp = (blockIdx.x * 256 + threadIdx.x) >> 5;
    if (warp >= n) return;
    int lane = threadIdx.x & 31;
    int sub  = lane >> 3;
    int c8   = lane & 7;

    const __half* zin_h = (const __half*)zin_v;
    const float*  zin_f = (const float*)zin_v;

    int beg = __ldg(&rowptr[warp]);
    int end = __ldg(&rowptr[warp + 1]);

    // hoist z0 row load (latency overlapped with edge loop)
    float z0v[8];
    load_row8_f(z0, warp, c8, z0v);

    float acc[8];
#pragma unroll
    for (int j = 0; j < 8; j++) acc[j] = 0.f;

    int i = beg + sub;
    // 4 edges per sub-group in flight (16 rows per warp)
    for (; i + 12 < end; i += 16) {
        int2 e0 = __ldg(&edges[i]);
        int2 e1 = __ldg(&edges[i + 4]);
        int2 e2 = __ldg(&edges[i + 8]);
        int2 e3 = __ldg(&edges[i + 12]);
        float v0[8], v1[8], v2[8], v3[8];
        if (IN_HALF) {
            load_row8_h(zin_h, e0.x, c8, v0); load_row8_h(zin_h, e1.x, c8, v1);
            load_row8_h(zin_h, e2.x, c8, v2); load_row8_h(zin_h, e3.x, c8, v3);
        } else {
            load_row8_f(zin_f, e0.x, c8, v0); load_row8_f(zin_f, e1.x, c8, v1);
            load_row8_f(zin_f, e2.x, c8, v2); load_row8_f(zin_f, e3.x, c8, v3);
        }
        float w0 = __int_as_float(e0.y), w1 = __int_as_float(e1.y);
        float w2 = __int_as_float(e2.y), w3 = __int_as_float(e3.y);
#pragma unroll
        for (int j = 0; j < 8; j++) acc[j] = fmaf(w0, v0[j], acc[j]);
#pragma unroll
        for (int j = 0; j < 8; j++) acc[j] = fmaf(w1, v1[j], acc[j]);
#pragma unroll
        for (int j = 0; j < 8; j++) acc[j] = fmaf(w2, v2[j], acc[j]);
#pragma unroll
        for (int j = 0; j < 8; j++) acc[j] = fmaf(w3, v3[j], acc[j]);
    }
    for (; i < end; i += 4) {
        int2 e0 = __ldg(&edges[i]);
        float v0[8];
        if (IN_HALF) load_row8_h(zin_h, e0.x, c8, v0);
        else         load_row8_f(zin_f, e0.x, c8, v0);
        float w0 = __int_as_float(e0.y);
#pragma unroll
        for (int j = 0; j < 8; j++) acc[j] = fmaf(w0, v0[j], acc[j]);
    }

    const unsigned FULL = 0xFFFFFFFFu;
#pragma unroll
    for (int j = 0; j < 8; j++) {
        acc[j] += __shfl_xor_sync(FULL, acc[j], 8);
        acc[j] += __shfl_xor_sync(FULL, acc[j], 16);
    }

    float o[8];
#pragma unroll
    for (int j = 0; j < 8; j++) o[j] = fmaf(c0, z0v[j], c1 * acc[j]);

    if (!LAST) {
        if (sub == 0) {
            __half2 h[4];
#pragma unroll
            for (int j = 0; j < 4; j++)
                h[j] = __floats2half2_rn(o[2 * j], o[2 * j + 1]);
            __half* zo = (__half*)zout_v;
            *(reinterpret_cast<float4*>(zo + (size_t)warp * NCLASS) + c8) =
                *reinterpret_cast<float4*>(h);
        }
    } else {
        float m = o[0];
#pragma unroll
        for (int j = 1; j < 8; j++) m = fmaxf(m, o[j]);
#pragma unroll
        for (int off = 1; off < 8; off <<= 1)
            m = fmaxf(m, __shfl_xor_sync(FULL, m, off));
        float s = 0.f;
#pragma unroll
        for (int j = 0; j < 8; j++) s += __expf(o[j] - m);
#pragma unroll
        for (int off = 1; off < 8; off <<= 1)
            s += __shfl_xor_sync(FULL, s, off);
        float l = m + __logf(s);
        if (sub == 0) {
            float* zo = (float*)zout_v;
            float4 r0 = make_float4(o[0] - l, o[1] - l, o[2] - l, o[3] - l);
            float4 r1 = make_float4(o[4] - l, o[5] - l, o[6] - l, o[7] - l);
            float4* p = reinterpret_cast<float4*>(zo + (size_t)warp * NCLASS);
            p[2 * c8]     = r0;
            p[2 * c8 + 1] = r1;
        }
    }
}

// =================================================================
// launch
// =================================================================
extern "C" void kernel_launch(void* const* d_in, const int* in_sizes, int n_in,
                              void* d_out, int out_size)
{
    const float* x   = (const float*)d_in[0];
    const int*   ei  = (const int*)  d_in[1];
    const float* ew  = (const float*)d_in[2];
    const float* W1  = (const float*)d_in[3];
    const float* W2  = (const float*)d_in[4];
    float*       out = (float*)d_out;

    const int n = in_sizes[0] / NFEAT;
    const int e = in_sizes[2];
    const int* src = ei;
    const int* dst = ei + e;

    float*  z0  = nullptr; cudaGetSymbolAddress((void**)&z0,  g_z0);
    __half* ya  = nullptr; cudaGetSymbolAddress((void**)&ya,  g_ya);
    __half* yb  = nullptr; cudaGetSymbolAddress((void**)&yb,  g_yb);
    int*    rp  = nullptr; cudaGetSymbolAddress((void**)&rp,  g_rowptr);
    int*    cur = nullptr; cudaGetSymbolAddress((void**)&cur, g_cursor);
    int*    bs  = nullptr; cudaGetSymbolAddress((void**)&bs,  g_bsums);
    int2*   edg = nullptr; cudaGetSymbolAddress((void**)&edg, g_edges);

    static cudaStream_t sG = nullptr;
    static cudaEvent_t  evF = nullptr, evG = nullptr;
    if (sG == nullptr) {
        cudaStreamCreateWithFlags(&sG, cudaStreamNonBlocking);
        cudaEventCreateWithFlags(&evF, cudaEventDisableTiming);
        cudaEventCreateWithFlags(&evG, cudaEventDisableTiming);
        cudaFuncSetAttribute(gemm_mma,
            cudaFuncAttributeMaxDynamicSharedMemorySize, GM_SMEM);
    }

    // ---- fork: tensor-core GEMM on side stream ----
    cudaEventRecord(evF, 0);
    cudaStreamWaitEvent(sG, evF, 0);
    gemm_mma<<<(n + 255) / 256, 256, GM_SMEM, sG>>>(x, W1, W2, z0, n);
    cudaEventRecord(evG, sG);

    // ---- CSR build on capture stream ----
    cudaMemsetAsync(cur, 0, (size_t)n * sizeof(int), 0);
    hist_dst<<<(e + 255) / 256, 256>>>(dst, cur, e);
    int nb = (n + SCAN_BLK - 1) / SCAN_BLK;
    scan1<<<nb, SCAN_BLK>>>(cur, rp, bs, n);
    scan2<<<1, 128>>>(bs, nb);
    scan3<<<(n + 256) / 256, 256>>>(rp, cur, bs, n, e);
    build_edges<<<(e + 255) / 256, 256>>>(src, dst, ew, cur, edg, e);

    // ---- join ----
    cudaStreamWaitEvent(0, evG, 0);

    // ---- APPNP, scaled-fp16 pipeline ----
    const float S = 16.0f;
    const int gblocks = (n * 32 + 255) / 256;

    gather_nodes<false, false><<<gblocks, 256>>>(
        edg, rp, z0, z0, ya, 1.0f / S, ALPHA / S, n);

    __half* bufs[2] = { ya, yb };
    float pw = S * S;
    for (int t = 1; t <= 8; t++) {
        __half* zin  = bufs[(t + 1) & 1];
        __half* zout = bufs[t & 1];
        gather_nodes<true, false><<<gblocks, 256>>>(
            edg, rp, zin, z0, zout, 1.0f / S, ALPHA / pw, n);
        pw *= S;
    }

    float S9 = 1.0f;
    for (int k = 0; k < 9; k++) S9 *= S;
    gather_nodes<true, true><<<gblocks, 256>>>(
        edg, rp, bufs[1], z0, out, S9, ALPHA, n);
}

// round 9
// speedup vs baseline: 1.1049x; 1.1049x over previous
#include <cuda_runtime.h>
#include <cuda_fp16.h>
#include <cuda_bf16.h>
#include <cstdint>

// ---------------- problem constants ----------------
#define MAXN    100000
#define MAXE    3200000
#define NFEAT   512
#define HID     64
#define NCLASS  64
#define ALPHA   0.1f
#define NITER   10
#define SCAN_BLK 1024

// ---------------- static device scratch ----------------
__device__ float  g_z0[MAXN * NCLASS];     // fp32 base prediction
__device__ __half g_y0[MAXN * NCLASS];     // fp16 cast of z0 (gather input, iter 0)
__device__ __half g_ya[MAXN * NCLASS];     // fp16 scaled z ping
__device__ __half g_yb[MAXN * NCLASS];     // fp16 scaled z pong
__device__ int    g_rowptr[MAXN + 1];
__device__ int    g_cursor[MAXN];
__device__ int    g_bsums[128];
__device__ int2   g_edges[MAXE];

// ================= mma.sync helpers (baseline sm_80+, works on sm_103) ====
__device__ __forceinline__ uint32_t smem_u32(const void* p) {
    uint32_t a;
    asm("{ .reg .u64 t; cvta.to.shared.u64 t, %1; cvt.u32.u64 %0, t; }"
        : "=r"(a) : "l"(p));
    return a;
}
__device__ __forceinline__ void ldsm_x4(uint32_t* r, uint32_t addr) {
    asm volatile("ldmatrix.sync.aligned.m8n8.x4.shared.b16 {%0,%1,%2,%3}, [%4];"
                 : "=r"(r[0]), "=r"(r[1]), "=r"(r[2]), "=r"(r[3]) : "r"(addr));
}
__device__ __forceinline__ void ldsm_x4_t(uint32_t* r, uint32_t addr) {
    asm volatile("ldmatrix.sync.aligned.m8n8.x4.trans.shared.b16 {%0,%1,%2,%3}, [%4];"
                 : "=r"(r[0]), "=r"(r[1]), "=r"(r[2]), "=r"(r[3]) : "r"(addr));
}
__device__ __forceinline__ void mma_bf16(
    float* d, const uint32_t* a, const uint32_t* b)
{
    asm volatile(
        "mma.sync.aligned.m16n8k16.row.col.f32.bf16.bf16.f32 "
        "{%0,%1,%2,%3}, {%4,%5,%6,%7}, {%8,%9}, {%0,%1,%2,%3};"
        : "+f"(d[0]), "+f"(d[1]), "+f"(d[2]), "+f"(d[3])
        : "r"(a[0]), "r"(a[1]), "r"(a[2]), "r"(a[3]), "r"(b[0]), "r"(b[1]));
}
__device__ __forceinline__ uint32_t pkbf2(float a, float b) {
    __nv_bfloat162 h = __floats2bfloat162_rn(a, b);
    return *reinterpret_cast<uint32_t*>(&h);
}

// =================================================================
// mma.sync fused GEMM: z0 = relu(x @ W1) @ W2, bf16 hi/lo 3-term split.
// =================================================================
#define GM_AHI 0
#define GM_ALO 36864
#define GM_BHI 73728
#define GM_BLO 82944
#define GM_SMEM 92160

__global__ __launch_bounds__(256) void gemm_mma(
    const float* __restrict__ X, const float* __restrict__ W1,
    const float* __restrict__ W2, float* __restrict__ Z0, int n)
{
    extern __shared__ char smc[];
    const uint32_t sb = smem_u32(smc);
    const int tid = threadIdx.x;
    const int wid = tid >> 5;
    const int l   = tid & 31;
    const int bm  = blockIdx.x * 256;
    const int wr  = wid * 32;

    const int arow = (l & 7) + ((l >> 3) & 1) * 8;
    const uint32_t akb = ((l >> 4) & 1) * 16;
    const uint32_t aoff0 = (uint32_t)(wr + arow) * 144 + akb;
    const uint32_t aoff1 = (uint32_t)(wr + 16 + arow) * 144 + akb;
    const uint32_t boff  = (uint32_t)arow * 144 + akb;

    float acc[2][8][4];
#pragma unroll
    for (int am = 0; am < 2; am++)
#pragma unroll
        for (int na = 0; na < 8; na++)
#pragma unroll
            for (int q = 0; q < 4; q++) acc[am][na][q] = 0.f;

    for (int c = 0; c < 8; c++) {
#pragma unroll
        for (int it = 0; it < 16; it++) {
            int idx = it * 256 + tid;
            int r   = idx >> 4;
            int c4  = idx & 15;
            int row = bm + r;
            float4 v = make_float4(0.f, 0.f, 0.f, 0.f);
            if (row < n)
                v = *reinterpret_cast<const float4*>(X + (size_t)row * NFEAT + c * 64 + c4 * 4);
            uint32_t h0 = pkbf2(v.x, v.y), h1 = pkbf2(v.z, v.w);
            __nv_bfloat162 bh0 = *reinterpret_cast<__nv_bfloat162*>(&h0);
            __nv_bfloat162 bh1 = *reinterpret_cast<__nv_bfloat162*>(&h1);
            float2 f0 = __bfloat1622float2(bh0);
            float2 f1 = __bfloat1622float2(bh1);
            uint32_t l0 = pkbf2(v.x - f0.x, v.y - f0.y);
            uint32_t l1 = pkbf2(v.z - f1.x, v.w - f1.y);
            uint32_t off = (uint32_t)r * 144 + c4 * 8;
            *reinterpret_cast<uint2*>(smc + GM_AHI + off) = make_uint2(h0, h1);
            *reinterpret_cast<uint2*>(smc + GM_ALO + off) = make_uint2(l0, l1);
        }
#pragma unroll
        for (int it = 0; it < 4; it++) {
            int idx = it * 256 + tid;
            int k   = idx >> 4;
            int c4  = idx & 15;
            float4 v = *reinterpret_cast<const float4*>(W1 + (size_t)(c * 64 + k) * HID + c4 * 4);
            uint32_t h0 = pkbf2(v.x, v.y), h1 = pkbf2(v.z, v.w);
            __nv_bfloat162 bh0 = *reinterpret_cast<__nv_bfloat162*>(&h0);
            __nv_bfloat162 bh1 = *reinterpret_cast<__nv_bfloat162*>(&h1);
            float2 f0 = __bfloat1622float2(bh0);
            float2 f1 = __bfloat1622float2(bh1);
            uint32_t l0 = pkbf2(v.x - f0.x, v.y - f0.y);
            uint32_t l1 = pkbf2(v.z - f1.x, v.w - f1.y);
            uint32_t off = (uint32_t)k * 144 + c4 * 8;
            *reinterpret_cast<uint2*>(smc + GM_BHI + off) = make_uint2(h0, h1);
            *reinterpret_cast<uint2*>(smc + GM_BLO + off) = make_uint2(l0, l1);
        }
        __syncthreads();

#pragma unroll
        for (int s = 0; s < 4; s++) {
            uint32_t ah0[4], ah1[4], al0[4], al1[4];
            ldsm_x4(ah0, sb + GM_AHI + aoff0 + s * 32);
            ldsm_x4(ah1, sb + GM_AHI + aoff1 + s * 32);
            ldsm_x4(al0, sb + GM_ALO + aoff0 + s * 32);
            ldsm_x4(al1, sb + GM_ALO + aoff1 + s * 32);
            uint32_t bh[8][2], bl[8][2];
#pragma unroll
            for (int p = 0; p < 4; p++) {
                uint32_t r4[4];
                ldsm_x4_t(r4, sb + GM_BHI + s * 2304 + p * 32 + boff);
                bh[2 * p][0] = r4[0]; bh[2 * p][1] = r4[1];
                bh[2 * p + 1][0] = r4[2]; bh[2 * p + 1][1] = r4[3];
                ldsm_x4_t(r4, sb + GM_BLO + s * 2304 + p * 32 + boff);
                bl[2 * p][0] = r4[0]; bl[2 * p][1] = r4[1];
                bl[2 * p + 1][0] = r4[2]; bl[2 * p + 1][1] = r4[3];
            }
#pragma unroll
            for (int na = 0; na < 8; na++) {
                mma_bf16(acc[0][na], ah0, bh[na]);
                mma_bf16(acc[1][na], ah1, bh[na]);
                mma_bf16(acc[0][na], al0, bh[na]);
                mma_bf16(acc[1][na], al1, bh[na]);
                mma_bf16(acc[0][na], ah0, bl[na]);
                mma_bf16(acc[1][na], ah1, bl[na]);
            }
        }
        __syncthreads();
    }

    // ---- phase 2 ----
    uint32_t a2h[2][4][4], a2l[2][4][4];
#pragma unroll
    for (int am = 0; am < 2; am++)
#pragma unroll
        for (int s = 0; s < 4; s++) {
            float v00 = fmaxf(acc[am][2 * s][0], 0.f);
            float v01 = fmaxf(acc[am][2 * s][1], 0.f);
            float v02 = fmaxf(acc[am][2 * s][2], 0.f);
            float v03 = fmaxf(acc[am][2 * s][3], 0.f);
            float v10 = fmaxf(acc[am][2 * s + 1][0], 0.f);
            float v11 = fmaxf(acc[am][2 * s + 1][1], 0.f);
            float v12 = fmaxf(acc[am][2 * s + 1][2], 0.f);
            float v13 = fmaxf(acc[am][2 * s + 1][3], 0.f);
            uint32_t h;
            h = pkbf2(v00, v01); a2h[am][s][0] = h;
            { __nv_bfloat162 b = *reinterpret_cast<__nv_bfloat162*>(&h); float2 f = __bfloat1622float2(b);
              a2l[am][s][0] = pkbf2(v00 - f.x, v01 - f.y); }
            h = pkbf2(v02, v03); a2h[am][s][1] = h;
            { __nv_bfloat162 b = *reinterpret_cast<__nv_bfloat162*>(&h); float2 f = __bfloat1622float2(b);
              a2l[am][s][1] = pkbf2(v02 - f.x, v03 - f.y); }
            h = pkbf2(v10, v11); a2h[am][s][2] = h;
            { __nv_bfloat162 b = *reinterpret_cast<__nv_bfloat162*>(&h); float2 f = __bfloat1622float2(b);
              a2l[am][s][2] = pkbf2(v10 - f.x, v11 - f.y); }
            h = pkbf2(v12, v13); a2h[am][s][3] = h;
            { __nv_bfloat162 b = *reinterpret_cast<__nv_bfloat162*>(&h); float2 f = __bfloat1622float2(b);
              a2l[am][s][3] = pkbf2(v12 - f.x, v13 - f.y); }
        }

#pragma unroll
    for (int am = 0; am < 2; am++)
#pragma unroll
        for (int na = 0; na < 8; na++)
#pragma unroll
            for (int q = 0; q < 4; q++) acc[am][na][q] = 0.f;

#pragma unroll
    for (int it = 0; it < 4; it++) {
        int idx = it * 256 + tid;
        int k   = idx >> 4;
        int c4  = idx & 15;
        float4 v = *reinterpret_cast<const float4*>(W2 + (size_t)k * NCLASS + c4 * 4);
        uint32_t h0 = pkbf2(v.x, v.y), h1 = pkbf2(v.z, v.w);
        __nv_bfloat162 bh0 = *reinterpret_cast<__nv_bfloat162*>(&h0);
        __nv_bfloat162 bh1 = *reinterpret_cast<__nv_bfloat162*>(&h1);
        float2 f0 = __bfloat1622float2(bh0);
        float2 f1 = __bfloat1622float2(bh1);
        uint32_t l0 = pkbf2(v.x - f0.x, v.y - f0.y);
        uint32_t l1 = pkbf2(v.z - f1.x, v.w - f1.y);
        uint32_t off = (uint32_t)k * 144 + c4 * 8;
        *reinterpret_cast<uint2*>(smc + GM_BHI + off) = make_uint2(h0, h1);
        *reinterpret_cast<uint2*>(smc + GM_BLO + off) = make_uint2(l0, l1);
    }
    __syncthreads();

#pragma unroll
    for (int s = 0; s < 4; s++) {
        uint32_t bh[8][2], bl[8][2];
#pragma unroll
        for (int p = 0; p < 4; p++) {
            uint32_t r4[4];
            ldsm_x4_t(r4, sb + GM_BHI + s * 2304 + p * 32 + boff);
            bh[2 * p][0] = r4[0]; bh[2 * p][1] = r4[1];
            bh[2 * p + 1][0] = r4[2]; bh[2 * p + 1][1] = r4[3];
            ldsm_x4_t(r4, sb + GM_BLO + s * 2304 + p * 32 + boff);
            bl[2 * p][0] = r4[0]; bl[2 * p][1] = r4[1];
            bl[2 * p + 1][0] = r4[2]; bl[2 * p + 1][1] = r4[3];
        }
#pragma unroll
        for (int na = 0; na < 8; na++) {
            mma_bf16(acc[0][na], a2h[0][s], bh[na]);
            mma_bf16(acc[1][na], a2h[1][s], bh[na]);
            mma_bf16(acc[0][na], a2l[0][s], bh[na]);
            mma_bf16(acc[1][na], a2l[1][s], bh[na]);
            mma_bf16(acc[0][na], a2h[0][s], bl[na]);
            mma_bf16(acc[1][na], a2h[1][s], bl[na]);
        }
    }

#pragma unroll
    for (int am = 0; am < 2; am++) {
        int r0 = bm + wr + am * 16 + (l >> 2);
        int col = (l & 3) * 2;
#pragma unroll
        for (int na = 0; na < 8; na++) {
            if (r0 < n)
                *reinterpret_cast<float2*>(Z0 + (size_t)r0 * NCLASS + na * 8 + col) =
                    make_float2(acc[am][na][0], acc[am][na][1]);
            if (r0 + 8 < n)
                *reinterpret_cast<float2*>(Z0 + (size_t)(r0 + 8) * NCLASS + na * 8 + col) =
                    make_float2(acc[am][na][2], acc[am][na][3]);
        }
    }
}

// =================================================================
// convert z0 (fp32) -> y0 (fp16); thread = 8 elements
// =================================================================
__global__ __launch_bounds__(256) void cvt_half(
    const float* __restrict__ z0, __half* __restrict__ y0, int total8)
{
    int i = blockIdx.x * 256 + threadIdx.x;
    if (i >= total8) return;
    const float4* p = reinterpret_cast<const float4*>(z0) + 2 * i;
    float4 a = p[0], b = p[1];
    __half2 h[4];
    h[0] = __floats2half2_rn(a.x, a.y);
    h[1] = __floats2half2_rn(a.z, a.w);
    h[2] = __floats2half2_rn(b.x, b.y);
    h[3] = __floats2half2_rn(b.z, b.w);
    reinterpret_cast<float4*>(y0)[i] = *reinterpret_cast<float4*>(h);
}

// =================================================================
// CSR construction
// =================================================================
__global__ __launch_bounds__(256) void zero_hist(int* __restrict__ cnt, int n)
{
    int i = blockIdx.x * 256 + threadIdx.x;
    if (i < n) cnt[i] = 0;
}

__global__ __launch_bounds__(256) void hist_dst(
    const int* __restrict__ dst, int* __restrict__ cnt, int e)
{
    int i = blockIdx.x * 256 + threadIdx.x;
    if (i < e) atomicAdd(&cnt[dst[i]], 1);
}

__global__ __launch_bounds__(SCAN_BLK) void scan1(
    const int* __restrict__ cnt, int* __restrict__ rowptr,
    int* __restrict__ bsums, int n)
{
    __shared__ int sh[SCAN_BLK];
    int t = threadIdx.x;
    int i = blockIdx.x * SCAN_BLK + t;
    int v = (i < n) ? cnt[i] : 0;
    sh[t] = v;
    __syncthreads();
#pragma unroll
    for (int off = 1; off < SCAN_BLK; off <<= 1) {
        int x = (t >= off) ? sh[t - off] : 0;
        __syncthreads();
        sh[t] += x;
        __syncthreads();
    }
    int incl = sh[t];
    if (i < n) rowptr[i] = incl - v;
    if (t == SCAN_BLK - 1) bsums[blockIdx.x] = incl;
}

__global__ __launch_bounds__(128) void scan2(int* __restrict__ bsums, int nb)
{
    __shared__ int sh[128];
    int t = threadIdx.x;
    int v = (t < nb) ? bsums[t] : 0;
    sh[t] = v;
    __syncthreads();
#pragma unroll
    for (int off = 1; off < 128; off <<= 1) {
        int x = (t >= off) ? sh[t - off] : 0;
        __syncthreads();
        sh[t] += x;
        __syncthreads();
    }
    if (t < nb) bsums[t] = sh[t] - v;
}

__global__ __launch_bounds__(256) void scan3(
    int* __restrict__ rowptr, int* __restrict__ cursor,
    const int* __restrict__ bsums, int n, int e)
{
    int i = blockIdx.x * 256 + threadIdx.x;
    if (i < n) {
        int v = rowptr[i] + bsums[i >> 10];
        rowptr[i] = v;
        cursor[i] = v;
    }
    if (i == n) rowptr[n] = e;
}

__global__ __launch_bounds__(256) void build_edges(
    const int* __restrict__ src, const int* __restrict__ dst,
    const float* __restrict__ ew, int* __restrict__ cursor,
    int2* __restrict__ edges, int e)
{
    int i = blockIdx.x * 256 + threadIdx.x;
    if (i < e) {
        int d = dst[i];
        int pos = atomicAdd(&cursor[d], 1);
        edges[pos] = make_int2(src[i], __float_as_int(ew[i]));
    }
}

// =================================================================
// gather (scaled fp16 pipeline): one warp per dst node.
// 4 sub-groups of 8 lanes; 2-deep unroll (round-7 proven config).
// =================================================================
__device__ __forceinline__ void load_row8_h(
    const __half* zin, int node, int c8, float* v)
{
    float4 raw = __ldg(reinterpret_cast<const float4*>(zin + (size_t)node * NCLASS) + c8);
    const __half2* h = reinterpret_cast<const __half2*>(&raw);
#pragma unroll
    for (int j = 0; j < 4; j++) {
        float2 f = __half22float2(h[j]);
        v[2 * j]     = f.x;
        v[2 * j + 1] = f.y;
    }
}
__device__ __forceinline__ void load_row8_f(
    const float* zin, int node, int c8, float* v)
{
    const float4* p = reinterpret_cast<const float4*>(zin + (size_t)node * NCLASS);
    float4 a = __ldg(p + 2 * c8);
    float4 b = __ldg(p + 2 * c8 + 1);
    v[0] = a.x; v[1] = a.y; v[2] = a.z; v[3] = a.w;
    v[4] = b.x; v[5] = b.y; v[6] = b.z; v[7] = b.w;
}

template<bool LAST>
__global__ __launch_bounds__(256) void gather_nodes(
    const int2* __restrict__ edges, const int* __restrict__ rowptr,
    const __half* __restrict__ zin, const float* __restrict__ z0,
    void* __restrict__ zout_v, float c1, float c0, int n)
{
    int warp = (blockIdx.x * 256 + threadIdx.x) >> 5;
    if (warp >= n) return;
    int lane = threadIdx.x & 31;
    int sub  = lane >> 3;
    int c8   = lane & 7;

    int beg = __ldg(&rowptr[warp]);
    int end = __ldg(&rowptr[warp + 1]);

    float acc[8];
#pragma unroll
    for (int j = 0; j < 8; j++) acc[j] = 0.f;

    int i = beg + sub;
    for (; i + 4 < end; i += 8) {
        int2 e0 = __ldg(&edges[i]);
        int2 e1 = __ldg(&edges[i + 4]);
        float v0[8], v1[8];
        load_row8_h(zin, e0.x, c8, v0);
        load_row8_h(zin, e1.x, c8, v1);
        float w0 = __int_as_float(e0.y);
        float w1 = __int_as_float(e1.y);
#pragma unroll
        for (int j = 0; j < 8; j++) acc[j] = fmaf(w0, v0[j], acc[j]);
#pragma unroll
        for (int j = 0; j < 8; j++) acc[j] = fmaf(w1, v1[j], acc[j]);
    }
    for (; i < end; i += 4) {
        int2 e0 = __ldg(&edges[i]);
        float v0[8];
        load_row8_h(zin, e0.x, c8, v0);
        float w0 = __int_as_float(e0.y);
#pragma unroll
        for (int j = 0; j < 8; j++) acc[j] = fmaf(w0, v0[j], acc[j]);
    }

    const unsigned FULL = 0xFFFFFFFFu;
#pragma unroll
    for (int j = 0; j < 8; j++) {
        acc[j] += __shfl_xor_sync(FULL, acc[j], 8);
        acc[j] += __shfl_xor_sync(FULL, acc[j], 16);
    }

    float z0v[8];
    load_row8_f(z0, warp, c8, z0v);
    float o[8];
#pragma unroll
    for (int j = 0; j < 8; j++) o[j] = fmaf(c0, z0v[j], c1 * acc[j]);

    if (!LAST) {
        if (sub == 0) {
            __half2 h[4];
#pragma unroll
            for (int j = 0; j < 4; j++)
                h[j] = __floats2half2_rn(o[2 * j], o[2 * j + 1]);
            __half* zo = (__half*)zout_v;
            *(reinterpret_cast<float4*>(zo + (size_t)warp * NCLASS) + c8) =
                *reinterpret_cast<float4*>(h);
        }
    } else {
        float m = o[0];
#pragma unroll
        for (int j = 1; j < 8; j++) m = fmaxf(m, o[j]);
#pragma unroll
        for (int off = 1; off < 8; off <<= 1)
            m = fmaxf(m, __shfl_xor_sync(FULL, m, off));
        float s = 0.f;
#pragma unroll
        for (int j = 0; j < 8; j++) s += __expf(o[j] - m);
#pragma unroll
        for (int off = 1; off < 8; off <<= 1)
            s += __shfl_xor_sync(FULL, s, off);
        float l = m + __logf(s);
        if (sub == 0) {
            float* zo = (float*)zout_v;
            float4 r0 = make_float4(o[0] - l, o[1] - l, o[2] - l, o[3] - l);
            float4 r1 = make_float4(o[4] - l, o[5] - l, o[6] - l, o[7] - l);
            float4* p = reinterpret_cast<float4*>(zo + (size_t)warp * NCLASS);
            p[2 * c8]     = r0;
            p[2 * c8 + 1] = r1;
        }
    }
}

// =================================================================
// launch
// =================================================================
extern "C" void kernel_launch(void* const* d_in, const int* in_sizes, int n_in,
                              void* d_out, int out_size)
{
    const float* x   = (const float*)d_in[0];
    const int*   ei  = (const int*)  d_in[1];
    const float* ew  = (const float*)d_in[2];
    const float* W1  = (const float*)d_in[3];
    const float* W2  = (const float*)d_in[4];
    float*       out = (float*)d_out;

    const int n = in_sizes[0] / NFEAT;
    const int e = in_sizes[2];
    const int* src = ei;
    const int* dst = ei + e;

    float*  z0  = nullptr; cudaGetSymbolAddress((void**)&z0,  g_z0);
    __half* y0  = nullptr; cudaGetSymbolAddress((void**)&y0,  g_y0);
    __half* ya  = nullptr; cudaGetSymbolAddress((void**)&ya,  g_ya);
    __half* yb  = nullptr; cudaGetSymbolAddress((void**)&yb,  g_yb);
    int*    rp  = nullptr; cudaGetSymbolAddress((void**)&rp,  g_rowptr);
    int*    cur = nullptr; cudaGetSymbolAddress((void**)&cur, g_cursor);
    int*    bs  = nullptr; cudaGetSymbolAddress((void**)&bs,  g_bsums);
    int2*   edg = nullptr; cudaGetSymbolAddress((void**)&edg, g_edges);

    static cudaStream_t sG = nullptr;
    static cudaEvent_t  evF = nullptr, evG = nullptr;
    if (sG == nullptr) {
        cudaStreamCreateWithFlags(&sG, cudaStreamNonBlocking);
        cudaEventCreateWithFlags(&evF, cudaEventDisableTiming);
        cudaEventCreateWithFlags(&evG, cudaEventDisableTiming);
        cudaFuncSetAttribute(gemm_mma,
            cudaFuncAttributeMaxDynamicSharedMemorySize, GM_SMEM);
    }

    // ---- fork: tensor-core GEMM + fp16 cast on side stream ----
    cudaEventRecord(evF, 0);
    cudaStreamWaitEvent(sG, evF, 0);
    gemm_mma<<<(n + 255) / 256, 256, GM_SMEM, sG>>>(x, W1, W2, z0, n);
    const int total8 = n * NCLASS / 8;
    cvt_half<<<(total8 + 255) / 256, 256, 0, sG>>>(z0, y0, total8);
    cudaEventRecord(evG, sG);

    // ---- CSR build on capture stream ----
    zero_hist<<<(n + 255) / 256, 256>>>(cur, n);
    hist_dst<<<(e + 255) / 256, 256>>>(dst, cur, e);
    int nb = (n + SCAN_BLK - 1) / SCAN_BLK;
    scan1<<<nb, SCAN_BLK>>>(cur, rp, bs, n);
    scan2<<<1, 128>>>(bs, nb);
    scan3<<<(n + 256) / 256, 256>>>(rp, cur, bs, n, e);
    build_edges<<<(e + 255) / 256, 256>>>(src, dst, ew, cur, edg, e);

    // ---- join ----
    cudaStreamWaitEvent(0, evG, 0);

    // ---- APPNP, scaled-fp16 pipeline ----
    // y_t = z_t / 16^t (exact power-of-two scaling)
    const float S = 16.0f;
    const int gblocks = (n * 32 + 255) / 256;

    // iter 0: y0 (=z0 cast) -> y1 (ya)
    gather_nodes<false><<<gblocks, 256>>>(
        edg, rp, y0, z0, ya, 1.0f / S, ALPHA / S, n);

    // iters 1..8: y_t -> y_{t+1}   (t=8 output lands in bufs[0]=ya)
    __half* bufs[2] = { ya, yb };
    float pw = S * S;
    for (int t = 1; t <= 8; t++) {
        __half* zin  = bufs[(t + 1) & 1];
        __half* zout = bufs[t & 1];
        gather_nodes<false><<<gblocks, 256>>>(
            edg, rp, zin, z0, zout, 1.0f / S, ALPHA / pw, n);
        pw *= S;
    }

    // iter 9 (final): input is y9 = bufs[0] (off-by-one FIXED), fused log_softmax
    float S9 = 1.0f;
    for (int k = 0; k < 9; k++) S9 *= S;
    gather_nodes<true><<<gblocks, 256>>>(
        edg, rp, bufs[0], z0, out, S9, ALPHA, n);
}

// round 10
// speedup vs baseline: 1.2725x; 1.1517x over previous
#include <cuda_runtime.h>
#include <cuda_fp16.h>
#include <cuda_bf16.h>
#include <cstdint>

// ---------------- problem constants ----------------
#define MAXN    100000
#define MAXE    3200000
#define NFEAT   512
#define HID     64
#define NCLASS  64
#define ALPHA   0.1f
#define NITER   10
#define SCAN_BLK 1024

// ---------------- static device scratch ----------------
__device__ float    g_z0[MAXN * NCLASS];   // fp32 base prediction
__device__ __half   g_y0[MAXN * NCLASS];   // fp16 cast of z0
__device__ __half   g_ya[MAXN * NCLASS];   // fp16 scaled z ping
__device__ __half   g_yb[MAXN * NCLASS];   // fp16 scaled z pong
__device__ int      g_rowptr[MAXN + 1];
__device__ int      g_cursor[MAXN];
__device__ int      g_bsums[128];
__device__ uint32_t g_edges[MAXE];         // packed: src(17b) << 15 | w_q15(15b)

// ================= mma.sync helpers (baseline sm_80+, works on sm_103) ====
__device__ __forceinline__ uint32_t smem_u32(const void* p) {
    uint32_t a;
    asm("{ .reg .u64 t; cvta.to.shared.u64 t, %1; cvt.u32.u64 %0, t; }"
        : "=r"(a) : "l"(p));
    return a;
}
__device__ __forceinline__ void ldsm_x4(uint32_t* r, uint32_t addr) {
    asm volatile("ldmatrix.sync.aligned.m8n8.x4.shared.b16 {%0,%1,%2,%3}, [%4];"
                 : "=r"(r[0]), "=r"(r[1]), "=r"(r[2]), "=r"(r[3]) : "r"(addr));
}
__device__ __forceinline__ void ldsm_x4_t(uint32_t* r, uint32_t addr) {
    asm volatile("ldmatrix.sync.aligned.m8n8.x4.trans.shared.b16 {%0,%1,%2,%3}, [%4];"
                 : "=r"(r[0]), "=r"(r[1]), "=r"(r[2]), "=r"(r[3]) : "r"(addr));
}
__device__ __forceinline__ void mma_bf16(
    float* d, const uint32_t* a, const uint32_t* b)
{
    asm volatile(
        "mma.sync.aligned.m16n8k16.row.col.f32.bf16.bf16.f32 "
        "{%0,%1,%2,%3}, {%4,%5,%6,%7}, {%8,%9}, {%0,%1,%2,%3};"
        : "+f"(d[0]), "+f"(d[1]), "+f"(d[2]), "+f"(d[3])
        : "r"(a[0]), "r"(a[1]), "r"(a[2]), "r"(a[3]), "r"(b[0]), "r"(b[1]));
}
__device__ __forceinline__ uint32_t pkbf2(float a, float b) {
    __nv_bfloat162 h = __floats2bfloat162_rn(a, b);
    return *reinterpret_cast<uint32_t*>(&h);
}

// =================================================================
// mma.sync fused GEMM: z0 = relu(x @ W1) @ W2, bf16 hi/lo 3-term split.
// =================================================================
#define GM_AHI 0
#define GM_ALO 36864
#define GM_BHI 73728
#define GM_BLO 82944
#define GM_SMEM 92160

__global__ __launch_bounds__(256) void gemm_mma(
    const float* __restrict__ X, const float* __restrict__ W1,
    const float* __restrict__ W2, float* __restrict__ Z0, int n)
{
    extern __shared__ char smc[];
    const uint32_t sb = smem_u32(smc);
    const int tid = threadIdx.x;
    const int wid = tid >> 5;
    const int l   = tid & 31;
    const int bm  = blockIdx.x * 256;
    const int wr  = wid * 32;

    const int arow = (l & 7) + ((l >> 3) & 1) * 8;
    const uint32_t akb = ((l >> 4) & 1) * 16;
    const uint32_t aoff0 = (uint32_t)(wr + arow) * 144 + akb;
    const uint32_t aoff1 = (uint32_t)(wr + 16 + arow) * 144 + akb;
    const uint32_t boff  = (uint32_t)arow * 144 + akb;

    float acc[2][8][4];
#pragma unroll
    for (int am = 0; am < 2; am++)
#pragma unroll
        for (int na = 0; na < 8; na++)
#pragma unroll
            for (int q = 0; q < 4; q++) acc[am][na][q] = 0.f;

    for (int c = 0; c < 8; c++) {
#pragma unroll
        for (int it = 0; it < 16; it++) {
            int idx = it * 256 + tid;
            int r   = idx >> 4;
            int c4  = idx & 15;
            int row = bm + r;
            float4 v = make_float4(0.f, 0.f, 0.f, 0.f);
            if (row < n)
                v = *reinterpret_cast<const float4*>(X + (size_t)row * NFEAT + c * 64 + c4 * 4);
            uint32_t h0 = pkbf2(v.x, v.y), h1 = pkbf2(v.z, v.w);
            __nv_bfloat162 bh0 = *reinterpret_cast<__nv_bfloat162*>(&h0);
            __nv_bfloat162 bh1 = *reinterpret_cast<__nv_bfloat162*>(&h1);
            float2 f0 = __bfloat1622float2(bh0);
            float2 f1 = __bfloat1622float2(bh1);
            uint32_t l0 = pkbf2(v.x - f0.x, v.y - f0.y);
            uint32_t l1 = pkbf2(v.z - f1.x, v.w - f1.y);
            uint32_t off = (uint32_t)r * 144 + c4 * 8;
            *reinterpret_cast<uint2*>(smc + GM_AHI + off) = make_uint2(h0, h1);
            *reinterpret_cast<uint2*>(smc + GM_ALO + off) = make_uint2(l0, l1);
        }
#pragma unroll
        for (int it = 0; it < 4; it++) {
            int idx = it * 256 + tid;
            int k   = idx >> 4;
            int c4  = idx & 15;
            float4 v = *reinterpret_cast<const float4*>(W1 + (size_t)(c * 64 + k) * HID + c4 * 4);
            uint32_t h0 = pkbf2(v.x, v.y), h1 = pkbf2(v.z, v.w);
            __nv_bfloat162 bh0 = *reinterpret_cast<__nv_bfloat162*>(&h0);
            __nv_bfloat162 bh1 = *reinterpret_cast<__nv_bfloat162*>(&h1);
            float2 f0 = __bfloat1622float2(bh0);
            float2 f1 = __bfloat1622float2(bh1);
            uint32_t l0 = pkbf2(v.x - f0.x, v.y - f0.y);
            uint32_t l1 = pkbf2(v.z - f1.x, v.w - f1.y);
            uint32_t off = (uint32_t)k * 144 + c4 * 8;
            *reinterpret_cast<uint2*>(smc + GM_BHI + off) = make_uint2(h0, h1);
            *reinterpret_cast<uint2*>(smc + GM_BLO + off) = make_uint2(l0, l1);
        }
        __syncthreads();

#pragma unroll
        for (int s = 0; s < 4; s++) {
            uint32_t ah0[4], ah1[4], al0[4], al1[4];
            ldsm_x4(ah0, sb + GM_AHI + aoff0 + s * 32);
            ldsm_x4(ah1, sb + GM_AHI + aoff1 + s * 32);
            ldsm_x4(al0, sb + GM_ALO + aoff0 + s * 32);
            ldsm_x4(al1, sb + GM_ALO + aoff1 + s * 32);
            uint32_t bh[8][2], bl[8][2];
#pragma unroll
            for (int p = 0; p < 4; p++) {
                uint32_t r4[4];
                ldsm_x4_t(r4, sb + GM_BHI + s * 2304 + p * 32 + boff);
                bh[2 * p][0] = r4[0]; bh[2 * p][1] = r4[1];
                bh[2 * p + 1][0] = r4[2]; bh[2 * p + 1][1] = r4[3];
                ldsm_x4_t(r4, sb + GM_BLO + s * 2304 + p * 32 + boff);
                bl[2 * p][0] = r4[0]; bl[2 * p][1] = r4[1];
                bl[2 * p + 1][0] = r4[2]; bl[2 * p + 1][1] = r4[3];
            }
#pragma unroll
            for (int na = 0; na < 8; na++) {
                mma_bf16(acc[0][na], ah0, bh[na]);
                mma_bf16(acc[1][na], ah1, bh[na]);
                mma_bf16(acc[0][na], al0, bh[na]);
                mma_bf16(acc[1][na], al1, bh[na]);
                mma_bf16(acc[0][na], ah0, bl[na]);
                mma_bf16(acc[1][na], ah1, bl[na]);
            }
        }
        __syncthreads();
    }

    // ---- phase 2 ----
    uint32_t a2h[2][4][4], a2l[2][4][4];
#pragma unroll
    for (int am = 0; am < 2; am++)
#pragma unroll
        for (int s = 0; s < 4; s++) {
            float v00 = fmaxf(acc[am][2 * s][0], 0.f);
            float v01 = fmaxf(acc[am][2 * s][1], 0.f);
            float v02 = fmaxf(acc[am][2 * s][2], 0.f);
            float v03 = fmaxf(acc[am][2 * s][3], 0.f);
            float v10 = fmaxf(acc[am][2 * s + 1][0], 0.f);
            float v11 = fmaxf(acc[am][2 * s + 1][1], 0.f);
            float v12 = fmaxf(acc[am][2 * s + 1][2], 0.f);
            float v13 = fmaxf(acc[am][2 * s + 1][3], 0.f);
            uint32_t h;
            h = pkbf2(v00, v01); a2h[am][s][0] = h;
            { __nv_bfloat162 b = *reinterpret_cast<__nv_bfloat162*>(&h); float2 f = __bfloat1622float2(b);
              a2l[am][s][0] = pkbf2(v00 - f.x, v01 - f.y); }
            h = pkbf2(v02, v03); a2h[am][s][1] = h;
            { __nv_bfloat162 b = *reinterpret_cast<__nv_bfloat162*>(&h); float2 f = __bfloat1622float2(b);
              a2l[am][s][1] = pkbf2(v02 - f.x, v03 - f.y); }
            h = pkbf2(v10, v11); a2h[am][s][2] = h;
            { __nv_bfloat162 b = *reinterpret_cast<__nv_bfloat162*>(&h); float2 f = __bfloat1622float2(b);
              a2l[am][s][2] = pkbf2(v10 - f.x, v11 - f.y); }
            h = pkbf2(v12, v13); a2h[am][s][3] = h;
            { __nv_bfloat162 b = *reinterpret_cast<__nv_bfloat162*>(&h); float2 f = __bfloat1622float2(b);
              a2l[am][s][3] = pkbf2(v12 - f.x, v13 - f.y); }
        }

#pragma unroll
    for (int am = 0; am < 2; am++)
#pragma unroll
        for (int na = 0; na < 8; na++)
#pragma unroll
            for (int q = 0; q < 4; q++) acc[am][na][q] = 0.f;

#pragma unroll
    for (int it = 0; it < 4; it++) {
        int idx = it * 256 + tid;
        int k   = idx >> 4;
        int c4  = idx & 15;
        float4 v = *reinterpret_cast<const float4*>(W2 + (size_t)k * NCLASS + c4 * 4);
        uint32_t h0 = pkbf2(v.x, v.y), h1 = pkbf2(v.z, v.w);
        __nv_bfloat162 bh0 = *reinterpret_cast<__nv_bfloat162*>(&h0);
        __nv_bfloat162 bh1 = *reinterpret_cast<__nv_bfloat162*>(&h1);
        float2 f0 = __bfloat1622float2(bh0);
        float2 f1 = __bfloat1622float2(bh1);
        uint32_t l0 = pkbf2(v.x - f0.x, v.y - f0.y);
        uint32_t l1 = pkbf2(v.z - f1.x, v.w - f1.y);
        uint32_t off = (uint32_t)k * 144 + c4 * 8;
        *reinterpret_cast<uint2*>(smc + GM_BHI + off) = make_uint2(h0, h1);
        *reinterpret_cast<uint2*>(smc + GM_BLO + off) = make_uint2(l0, l1);
    }
    __syncthreads();

#pragma unroll
    for (int s = 0; s < 4; s++) {
        uint32_t bh[8][2], bl[8][2];
#pragma unroll
        for (int p = 0; p < 4; p++) {
            uint32_t r4[4];
            ldsm_x4_t(r4, sb + GM_BHI + s * 2304 + p * 32 + boff);
            bh[2 * p][0] = r4[0]; bh[2 * p][1] = r4[1];
            bh[2 * p + 1][0] = r4[2]; bh[2 * p + 1][1] = r4[3];
            ldsm_x4_t(r4, sb + GM_BLO + s * 2304 + p * 32 + boff);
            bl[2 * p][0] = r4[0]; bl[2 * p][1] = r4[1];
            bl[2 * p + 1][0] = r4[2]; bl[2 * p + 1][1] = r4[3];
        }
#pragma unroll
        for (int na = 0; na < 8; na++) {
            mma_bf16(acc[0][na], a2h[0][s], bh[na]);
            mma_bf16(acc[1][na], a2h[1][s], bh[na]);
            mma_bf16(acc[0][na], a2l[0][s], bh[na]);
            mma_bf16(acc[1][na], a2l[1][s], bh[na]);
            mma_bf16(acc[0][na], a2h[0][s], bl[na]);
            mma_bf16(acc[1][na], a2h[1][s], bl[na]);
        }
    }

#pragma unroll
    for (int am = 0; am < 2; am++) {
        int r0 = bm + wr + am * 16 + (l >> 2);
        int col = (l & 3) * 2;
#pragma unroll
        for (int na = 0; na < 8; na++) {
            if (r0 < n)
                *reinterpret_cast<float2*>(Z0 + (size_t)r0 * NCLASS + na * 8 + col) =
                    make_float2(acc[am][na][0], acc[am][na][1]);
            if (r0 + 8 < n)
                *reinterpret_cast<float2*>(Z0 + (size_t)(r0 + 8) * NCLASS + na * 8 + col) =
                    make_float2(acc[am][na][2], acc[am][na][3]);
        }
    }
}

// =================================================================
// convert z0 (fp32) -> y0 (fp16); thread = 8 elements
// =================================================================
__global__ __launch_bounds__(256) void cvt_half(
    const float* __restrict__ z0, __half* __restrict__ y0, int total8)
{
    int i = blockIdx.x * 256 + threadIdx.x;
    if (i >= total8) return;
    const float4* p = reinterpret_cast<const float4*>(z0) + 2 * i;
    float4 a = p[0], b = p[1];
    __half2 h[4];
    h[0] = __floats2half2_rn(a.x, a.y);
    h[1] = __floats2half2_rn(a.z, a.w);
    h[2] = __floats2half2_rn(b.x, b.y);
    h[3] = __floats2half2_rn(b.z, b.w);
    reinterpret_cast<float4*>(y0)[i] = *reinterpret_cast<float4*>(h);
}

// =================================================================
// CSR construction
// =================================================================
__global__ __launch_bounds__(256) void zero_hist(int* __restrict__ cnt, int n)
{
    int i = blockIdx.x * 256 + threadIdx.x;
    if (i < n) cnt[i] = 0;
}

__global__ __launch_bounds__(256) void hist_dst(
    const int* __restrict__ dst, int* __restrict__ cnt, int e)
{
    int i = blockIdx.x * 256 + threadIdx.x;
    if (i < e) atomicAdd(&cnt[dst[i]], 1);
}

__global__ __launch_bounds__(SCAN_BLK) void scan1(
    const int* __restrict__ cnt, int* __restrict__ rowptr,
    int* __restrict__ bsums, int n)
{
    __shared__ int sh[SCAN_BLK];
    int t = threadIdx.x;
    int i = blockIdx.x * SCAN_BLK + t;
    int v = (i < n) ? cnt[i] : 0;
    sh[t] = v;
    __syncthreads();
#pragma unroll
    for (int off = 1; off < SCAN_BLK; off <<= 1) {
        int x = (t >= off) ? sh[t - off] : 0;
        __syncthreads();
        sh[t] += x;
        __syncthreads();
    }
    int incl = sh[t];
    if (i < n) rowptr[i] = incl - v;
    if (t == SCAN_BLK - 1) bsums[blockIdx.x] = incl;
}

__global__ __launch_bounds__(128) void scan2(int* __restrict__ bsums, int nb)
{
    __shared__ int sh[128];
    int t = threadIdx.x;
    int v = (t < nb) ? bsums[t] : 0;
    sh[t] = v;
    __syncthreads();
#pragma unroll
    for (int off = 1; off < 128; off <<= 1) {
        int x = (t >= off) ? sh[t - off] : 0;
        __syncthreads();
        sh[t] += x;
        __syncthreads();
    }
    if (t < nb) bsums[t] = sh[t] - v;
}

__global__ __launch_bounds__(256) void scan3(
    int* __restrict__ rowptr, int* __restrict__ cursor,
    const int* __restrict__ bsums, int n, int e)
{
    int i = blockIdx.x * 256 + threadIdx.x;
    if (i < n) {
        int v = rowptr[i] + bsums[i >> 10];
        rowptr[i] = v;
        cursor[i] = v;
    }
    if (i == n) rowptr[n] = e;
}

// pack: src (17 bits, <<15) | weight q15 (15 bits)
__global__ __launch_bounds__(256) void build_edges(
    const int* __restrict__ src, const int* __restrict__ dst,
    const float* __restrict__ ew, int* __restrict__ cursor,
    uint32_t* __restrict__ edges, int e)
{
    int i = blockIdx.x * 256 + threadIdx.x;
    if (i < e) {
        int d = dst[i];
        int pos = atomicAdd(&cursor[d], 1);
        int q = __float2int_rn(ew[i] * 32768.0f);
        if (q > 32767) q = 32767;
        if (q < 0) q = 0;
        edges[pos] = ((uint32_t)src[i] << 15) | (uint32_t)q;
    }
}

// =================================================================
// gather (scaled fp16 pipeline): one warp per dst node.
// 4 sub-groups of 8 lanes; 2-deep unroll; packed 4B edges.
// Injection: fp16 y0 for middle iters, fp32 z0 for final.
// =================================================================
__device__ __forceinline__ void load_row8_h(
    const __half* zin, uint32_t node, int c8, float* v)
{
    float4 raw = __ldg(reinterpret_cast<const float4*>(zin + (size_t)node * NCLASS) + c8);
    const __half2* h = reinterpret_cast<const __half2*>(&raw);
#pragma unroll
    for (int j = 0; j < 4; j++) {
        float2 f = __half22float2(h[j]);
        v[2 * j]     = f.x;
        v[2 * j + 1] = f.y;
    }
}
__device__ __forceinline__ void load_row8_f(
    const float* zin, int node, int c8, float* v)
{
    const float4* p = reinterpret_cast<const float4*>(zin + (size_t)node * NCLASS);
    float4 a = __ldg(p + 2 * c8);
    float4 b = __ldg(p + 2 * c8 + 1);
    v[0] = a.x; v[1] = a.y; v[2] = a.z; v[3] = a.w;
    v[4] = b.x; v[5] = b.y; v[6] = b.z; v[7] = b.w;
}

#define WQ 3.0517578125e-5f   // 1/32768

template<bool LAST>
__global__ __launch_bounds__(256) void gather_nodes(
    const uint32_t* __restrict__ edges, const int* __restrict__ rowptr,
    const __half* __restrict__ zin, const __half* __restrict__ y0,
    const float* __restrict__ z0, void* __restrict__ zout_v,
    float c1, float c0, int n)
{
    int warp = (blockIdx.x * 256 + threadIdx.x) >> 5;
    if (warp >= n) return;
    int lane = threadIdx.x & 31;
    int sub  = lane >> 3;
    int c8   = lane & 7;

    int beg = __ldg(&rowptr[warp]);
    int end = __ldg(&rowptr[warp + 1]);

    float acc[8];
#pragma unroll
    for (int j = 0; j < 8; j++) acc[j] = 0.f;

    int i = beg + sub;
    for (; i + 4 < end; i += 8) {
        uint32_t e0 = __ldg(&edges[i]);
        uint32_t e1 = __ldg(&edges[i + 4]);
        float v0[8], v1[8];
        load_row8_h(zin, e0 >> 15, c8, v0);
        load_row8_h(zin, e1 >> 15, c8, v1);
        float w0 = (float)(e0 & 0x7FFFu) * WQ;
        float w1 = (float)(e1 & 0x7FFFu) * WQ;
#pragma unroll
        for (int j = 0; j < 8; j++) acc[j] = fmaf(w0, v0[j], acc[j]);
#pragma unroll
        for (int j = 0; j < 8; j++) acc[j] = fmaf(w1, v1[j], acc[j]);
    }
    for (; i < end; i += 4) {
        uint32_t e0 = __ldg(&edges[i]);
        float v0[8];
        load_row8_h(zin, e0 >> 15, c8, v0);
        float w0 = (float)(e0 & 0x7FFFu) * WQ;
#pragma unroll
        for (int j = 0; j < 8; j++) acc[j] = fmaf(w0, v0[j], acc[j]);
    }

    const unsigned FULL = 0xFFFFFFFFu;
#pragma unroll
    for (int j = 0; j < 8; j++) {
        acc[j] += __shfl_xor_sync(FULL, acc[j], 8);
        acc[j] += __shfl_xor_sync(FULL, acc[j], 16);
    }

    float z0v[8];
    if (LAST) load_row8_f(z0, warp, c8, z0v);
    else      load_row8_h(y0, (uint32_t)warp, c8, z0v);
    float o[8];
#pragma unroll
    for (int j = 0; j < 8; j++) o[j] = fmaf(c0, z0v[j], c1 * acc[j]);

    if (!LAST) {
        if (sub == 0) {
            __half2 h[4];
#pragma unroll
            for (int j = 0; j < 4; j++)
                h[j] = __floats2half2_rn(o[2 * j], o[2 * j + 1]);
            __half* zo = (__half*)zout_v;
            *(reinterpret_cast<float4*>(zo + (size_t)warp * NCLASS) + c8) =
                *reinterpret_cast<float4*>(h);
        }
    } else {
        float m = o[0];
#pragma unroll
        for (int j = 1; j < 8; j++) m = fmaxf(m, o[j]);
#pragma unroll
        for (int off = 1; off < 8; off <<= 1)
            m = fmaxf(m, __shfl_xor_sync(FULL, m, off));
        float s = 0.f;
#pragma unroll
        for (int j = 0; j < 8; j++) s += __expf(o[j] - m);
#pragma unroll
        for (int off = 1; off < 8; off <<= 1)
            s += __shfl_xor_sync(FULL, s, off);
        float l = m + __logf(s);
        if (sub == 0) {
            float* zo = (float*)zout_v;
            float4 r0 = make_float4(o[0] - l, o[1] - l, o[2] - l, o[3] - l);
            float4 r1 = make_float4(o[4] - l, o[5] - l, o[6] - l, o[7] - l);
            float4* p = reinterpret_cast<float4*>(zo + (size_t)warp * NCLASS);
            p[2 * c8]     = r0;
            p[2 * c8 + 1] = r1;
        }
    }
}

// =================================================================
// launch
// =================================================================
extern "C" void kernel_launch(void* const* d_in, const int* in_sizes, int n_in,
                              void* d_out, int out_size)
{
    const float* x   = (const float*)d_in[0];
    const int*   ei  = (const int*)  d_in[1];
    const float* ew  = (const float*)d_in[2];
    const float* W1  = (const float*)d_in[3];
    const float* W2  = (const float*)d_in[4];
    float*       out = (float*)d_out;

    const int n = in_sizes[0] / NFEAT;
    const int e = in_sizes[2];
    const int* src = ei;
    const int* dst = ei + e;

    float*    z0  = nullptr; cudaGetSymbolAddress((void**)&z0,  g_z0);
    __half*   y0  = nullptr; cudaGetSymbolAddress((void**)&y0,  g_y0);
    __half*   ya  = nullptr; cudaGetSymbolAddress((void**)&ya,  g_ya);
    __half*   yb  = nullptr; cudaGetSymbolAddress((void**)&yb,  g_yb);
    int*      rp  = nullptr; cudaGetSymbolAddress((void**)&rp,  g_rowptr);
    int*      cur = nullptr; cudaGetSymbolAddress((void**)&cur, g_cursor);
    int*      bs  = nullptr; cudaGetSymbolAddress((void**)&bs,  g_bsums);
    uint32_t* edg = nullptr; cudaGetSymbolAddress((void**)&edg, g_edges);

    static cudaStream_t sG = nullptr;
    static cudaEvent_t  evF = nullptr, evG = nullptr;
    if (sG == nullptr) {
        cudaStreamCreateWithFlags(&sG, cudaStreamNonBlocking);
        cudaEventCreateWithFlags(&evF, cudaEventDisableTiming);
        cudaEventCreateWithFlags(&evG, cudaEventDisableTiming);
        cudaFuncSetAttribute(gemm_mma,
            cudaFuncAttributeMaxDynamicSharedMemorySize, GM_SMEM);
    }

    // ---- fork: tensor-core GEMM + fp16 cast on side stream ----
    cudaEventRecord(evF, 0);
    cudaStreamWaitEvent(sG, evF, 0);
    gemm_mma<<<(n + 255) / 256, 256, GM_SMEM, sG>>>(x, W1, W2, z0, n);
    const int total8 = n * NCLASS / 8;
    cvt_half<<<(total8 + 255) / 256, 256, 0, sG>>>(z0, y0, total8);
    cudaEventRecord(evG, sG);

    // ---- CSR build on capture stream ----
    zero_hist<<<(n + 255) / 256, 256>>>(cur, n);
    hist_dst<<<(e + 255) / 256, 256>>>(dst, cur, e);
    int nb = (n + SCAN_BLK - 1) / SCAN_BLK;
    scan1<<<nb, SCAN_BLK>>>(cur, rp, bs, n);
    scan2<<<1, 128>>>(bs, nb);
    scan3<<<(n + 256) / 256, 256>>>(rp, cur, bs, n, e);
    build_edges<<<(e + 255) / 256, 256>>>(src, dst, ew, cur, edg, e);

    // ---- join ----
    cudaStreamWaitEvent(0, evG, 0);

    // ---- APPNP, scaled-fp16 pipeline ----
    // y_t = z_t / 16^t (exact power-of-two scaling)
    const float S = 16.0f;
    const int gblocks = (n * 32 + 255) / 256;

    // iter 0: y0 -> y1 (ya)
    gather_nodes<false><<<gblocks, 256>>>(
        edg, rp, y0, y0, z0, ya, 1.0f / S, ALPHA / S, n);

    // iters 1..8: y_t -> y_{t+1}   (t=8 output lands in bufs[0]=ya)
    __half* bufs[2] = { ya, yb };
    float pw = S * S;
    for (int t = 1; t <= 8; t++) {
        __half* zin  = bufs[(t + 1) & 1];
        __half* zout = bufs[t & 1];
        gather_nodes<false><<<gblocks, 256>>>(
            edg, rp, zin, y0, z0, zout, 1.0f / S, ALPHA / pw, n);
        pw *= S;
    }

    // iter 9 (final): input y9 = bufs[0], fp32 z0 injection, fused log_softmax
    float S9 = 1.0f;
    for (int k = 0; k < 9; k++) S9 *= S;
    gather_nodes<true><<<gblocks, 256>>>(
        edg, rp, bufs[0], y0, z0, out, S9, ALPHA, n);
}